// round 3
// baseline (speedup 1.0000x reference)
#include <cuda_runtime.h>

#define D    128
#define NMAX 50000
#define EMAX 800000

// ---------------- scratch (device globals: allocation-free) ----------------
__device__ __align__(16) float g_A[(size_t)NMAX * D];   // h_lin / hm
__device__ __align__(16) float g_B[(size_t)NMAX * D];   // h (post-relu)
__device__ __align__(16) float g_Wcat[D * D];           // [w_mu | w_ls]
__device__ int   g_degi[NMAX];
__device__ float g_dis[NMAX];
__device__ int   g_off[NMAX];
__device__ int   g_cur[NMAX];
__device__ __align__(16) int2 g_edge[EMAX];             // (src, norm-as-int) CSR order
__device__ int   g_src[EMAX];
__device__ int   g_dst[EMAX];
__device__ int   g_is32;

// ---------------- edge-index dtype detection ----------------
__global__ void k_detect(const long long* __restrict__ ei, int total64, int n) {
    __shared__ int bad;
    if (threadIdx.x == 0) bad = 0;
    __syncthreads();
    int lim = total64 < 1024 ? total64 : 1024;
    for (int i = threadIdx.x; i < lim; i += blockDim.x) {
        long long v = ei[i];
        if (v < 0 || v >= (long long)n) bad = 1;
    }
    __syncthreads();
    if (threadIdx.x == 0) g_is32 = bad;
}

// ---------------- CSR build ----------------
__global__ void k_prep(const void* __restrict__ ei, int E, int n) {
    int i = blockIdx.x * blockDim.x + threadIdx.x;
    if (i < E) {
        int s, d;
        if (g_is32) {
            const int* e32 = (const int*)ei;
            s = e32[i];
            d = e32[E + i];
        } else {
            const long long* e64 = (const long long*)ei;
            s = (int)e64[i];
            d = (int)e64[(size_t)E + i];
        }
        g_src[i] = s;
        g_dst[i] = d;
    }
    if (i < n) g_degi[i] = 0;
}

__global__ void k_deg(int E) {
    int e = blockIdx.x * blockDim.x + threadIdx.x;
    if (e < E) atomicAdd(&g_degi[g_dst[e]], 1);
}

// Single block: exclusive scan of deg -> off/cur, plus dis = rsqrt(deg).
__global__ void k_scan(int n) {
    __shared__ int part[1024];
    int t = threadIdx.x;
    int chunk = (n + 1023) / 1024;
    int lo = t * chunk;
    int hi = lo + chunk; if (hi > n) hi = n;
    int s = 0;
    for (int i = lo; i < hi; i++) s += g_degi[i];
    part[t] = s;
    __syncthreads();
    for (int off = 1; off < 1024; off <<= 1) {
        int v = (t >= off) ? part[t - off] : 0;
        __syncthreads();
        part[t] += v;
        __syncthreads();
    }
    int run = (t > 0) ? part[t - 1] : 0;
    for (int i = lo; i < hi; i++) {
        int d = g_degi[i];
        g_off[i] = run;
        g_cur[i] = run;
        g_dis[i] = (d > 0) ? rsqrtf((float)d) : 0.0f;
        run += d;
    }
}

__global__ void k_fill(int E) {
    int e = blockIdx.x * blockDim.x + threadIdx.x;
    if (e < E) {
        int s = g_src[e], d = g_dst[e];
        int pos = atomicAdd(&g_cur[d], 1);
        float nm = g_dis[s] * g_dis[d];
        g_edge[pos] = make_int2(s, __float_as_int(nm));
    }
}

__global__ void k_cat(const float* __restrict__ wmu, const float* __restrict__ wls) {
    int i = blockIdx.x * blockDim.x + threadIdx.x;
    if (i < D * D) {
        int k = i >> 7, c = i & 127;
        g_Wcat[i] = (c < 64) ? wmu[k * 64 + c] : wls[k * 64 + (c - 64)];
    }
}

// ---------------- dense GEMM: OUT[n,128] = X[n,128] @ W[128,128] ----------------
// 256 threads, 128x128 block tile, 8x8 thread tile (cols strided by 16).
__global__ void __launch_bounds__(256, 2)
k_gemm(const float* __restrict__ X, const float* __restrict__ W,
       float* __restrict__ OUT, int nrows) {
    __shared__ float Ws[16][128];
    __shared__ float Xs[16][133];

    int tx = threadIdx.x;
    int c0 = tx & 15;            // cols c0 + 16*j, j=0..7
    int r0 = (tx >> 4) * 8;      // rows r0..r0+7
    int rowBase = blockIdx.x * 128;

    float acc[8][8];
#pragma unroll
    for (int i = 0; i < 8; i++)
#pragma unroll
        for (int j = 0; j < 8; j++) acc[i][j] = 0.0f;

    for (int kk = 0; kk < 128; kk += 16) {
        // W slab: rows kk..kk+15 contiguous (2048 floats = 512 float4)
        const float4* wg = (const float4*)(W + (size_t)kk * 128);
        float4* ws4 = (float4*)&Ws[0][0];
        ws4[tx] = wg[tx];
        ws4[tx + 256] = wg[tx + 256];

        // X slab transposed: Xs[k][row]
#pragma unroll
        for (int it = 0; it < 2; it++) {
            int idx = tx + it * 256;      // 0..511
            int row = idx >> 2;           // 0..127
            int k4  = idx & 3;            // which float4 of the 16 k's
            int grow = rowBase + row;
            float4 v = (grow < nrows)
                       ? ((const float4*)(X + (size_t)grow * 128 + kk))[k4]
                       : make_float4(0.f, 0.f, 0.f, 0.f);
            Xs[k4 * 4 + 0][row] = v.x;
            Xs[k4 * 4 + 1][row] = v.y;
            Xs[k4 * 4 + 2][row] = v.z;
            Xs[k4 * 4 + 3][row] = v.w;
        }
        __syncthreads();

#pragma unroll
        for (int k = 0; k < 16; k++) {
            float xv[8], wv[8];
#pragma unroll
            for (int i = 0; i < 8; i++) xv[i] = Xs[k][r0 + i];
#pragma unroll
            for (int j = 0; j < 8; j++) wv[j] = Ws[k][c0 + 16 * j];
#pragma unroll
            for (int i = 0; i < 8; i++)
#pragma unroll
                for (int j = 0; j < 8; j++)
                    acc[i][j] += xv[i] * wv[j];
        }
        __syncthreads();
    }

#pragma unroll
    for (int i = 0; i < 8; i++) {
        int grow = rowBase + r0 + i;
        if (grow < nrows) {
            float* o = OUT + (size_t)grow * 128;
#pragma unroll
            for (int j = 0; j < 8; j++) o[c0 + 16 * j] = acc[i][j];
        }
    }
}

// ---------------- warp-per-node gather aggregation ----------------
// Layer 1: out = relu(sum(norm*h[src]) + b1)
__global__ void k_gather_relu(const float* __restrict__ h, float* __restrict__ out,
                              const float* __restrict__ b1, int n) {
    int w = (blockIdx.x * blockDim.x + threadIdx.x) >> 5;
    int lane = threadIdx.x & 31;
    if (w >= n) return;
    int start = g_off[w], deg = g_degi[w];
    float4 acc = make_float4(0.f, 0.f, 0.f, 0.f);
#pragma unroll 4
    for (int i = 0; i < deg; i++) {
        int2 ed = __ldg(&g_edge[start + i]);
        float nm = __int_as_float(ed.y);
        float4 v = ((const float4*)(h + (size_t)ed.x * 128))[lane];
        acc.x += nm * v.x; acc.y += nm * v.y;
        acc.z += nm * v.z; acc.w += nm * v.w;
    }
    float4 b = ((const float4*)b1)[lane];
    acc.x = fmaxf(acc.x + b.x, 0.f);
    acc.y = fmaxf(acc.y + b.y, 0.f);
    acc.z = fmaxf(acc.z + b.z, 0.f);
    acc.w = fmaxf(acc.w + b.w, 0.f);
    ((float4*)(out + (size_t)w * 128))[lane] = acc;
}

// Layer 2: split hm (mu|ls concat) into the two output halves, bias fused.
__global__ void k_gather_out(const float* __restrict__ h, float* __restrict__ out,
                             const float* __restrict__ bmu, const float* __restrict__ bls,
                             int half, int n) {
    int w = (blockIdx.x * blockDim.x + threadIdx.x) >> 5;
    int lane = threadIdx.x & 31;
    if (w >= n) return;
    int start = g_off[w], deg = g_degi[w];
    float4 acc = make_float4(0.f, 0.f, 0.f, 0.f);
#pragma unroll 4
    for (int i = 0; i < deg; i++) {
        int2 ed = __ldg(&g_edge[start + i]);
        float nm = __int_as_float(ed.y);
        float4 v = ((const float4*)(h + (size_t)w * 0 + (size_t)ed.x * 128))[lane];
        acc.x += nm * v.x; acc.y += nm * v.y;
        acc.z += nm * v.z; acc.w += nm * v.w;
    }
    int col = lane * 4;
    float4 b; float* p;
    if (col < 64) {
        b = ((const float4*)bmu)[lane];
        p = out + (size_t)w * 64 + col;
    } else {
        b = ((const float4*)bls)[lane - 16];
        p = out + half + (size_t)w * 64 + (col - 64);
    }
    acc.x += b.x; acc.y += b.y; acc.z += b.z; acc.w += b.w;
    *(float4*)p = acc;
}

// ---------------- launch ----------------
extern "C" void kernel_launch(void* const* d_in, const int* in_sizes, int n_in,
                              void* d_out, int out_size) {
    const float* x   = (const float*)d_in[0];
    const void*  ei  = d_in[1];
    const float* w1  = (const float*)d_in[2];
    const float* b1  = (const float*)d_in[3];
    const float* wmu = (const float*)d_in[4];
    const float* bmu = (const float*)d_in[5];
    const float* wls = (const float*)d_in[6];
    const float* bls = (const float*)d_in[7];
    float* out = (float*)d_out;

    int n = in_sizes[0] / D;          // 50000
    int E = in_sizes[1] / 2;          // 800000
    int half = out_size / 2;          // n*64

    float *A, *B, *Wc;
    cudaGetSymbolAddress((void**)&A,  g_A);
    cudaGetSymbolAddress((void**)&B,  g_B);
    cudaGetSymbolAddress((void**)&Wc, g_Wcat);

    const int T = 256;
    int mEn = (E > n) ? E : n;

    // CSR build
    k_detect<<<1, 256>>>((const long long*)ei, E, n);
    k_prep<<<(mEn + T - 1) / T, T>>>(ei, E, n);
    k_deg<<<(E + T - 1) / T, T>>>(E);
    k_scan<<<1, 1024>>>(n);
    k_fill<<<(E + T - 1) / T, T>>>(E);
    k_cat<<<(D * D + T - 1) / T, T>>>(wmu, wls);

    int gatherBlocks = (n * 32 + T - 1) / T;

    // layer 1: h_lin = x @ w1 ; h = relu(gather + b1)
    k_gemm<<<(n + 127) / 128, T>>>(x, w1, A, n);
    k_gather_relu<<<gatherBlocks, T>>>(A, B, b1, n);

    // layer 2 (fused mu|logstd): hm = h @ [w_mu|w_ls] ; out = gather + bias
    k_gemm<<<(n + 127) / 128, T>>>(B, Wc, A, n);
    k_gather_out<<<gatherBlocks, T>>>(A, out, bmu, bls, half, n);
}

// round 4
// speedup vs baseline: 1.4580x; 1.4580x over previous
#include <cuda_runtime.h>

#define D    128
#define NMAX 50000
#define EMAX 800000
#define NBMAX 64   // ceil(NMAX/1024)=49

// ---------------- scratch (device globals: allocation-free) ----------------
__device__ __align__(16) float g_A[(size_t)NMAX * D];   // h_lin / hm
__device__ __align__(16) float g_B[(size_t)NMAX * D];   // h (post-relu)
__device__ __align__(16) float g_Wcat[D * D];           // [w_mu | w_ls]
__device__ int   g_degi[NMAX];
__device__ float g_dis[NMAX];
__device__ int   g_off[NMAX];
__device__ int   g_cur[NMAX];
__device__ int   g_bsum[NBMAX];
__device__ int   g_bsumex[NBMAX];
__device__ __align__(16) int2 g_edge[EMAX];             // (src, norm-as-int) CSR order
__device__ int   g_src[EMAX];
__device__ int   g_dst[EMAX];
__device__ int   g_is32;

// ---------------- edge-index dtype detection ----------------
__global__ void k_detect(const long long* __restrict__ ei, int total64, int n) {
    __shared__ int bad;
    if (threadIdx.x == 0) bad = 0;
    __syncthreads();
    int lim = total64 < 1024 ? total64 : 1024;
    for (int i = threadIdx.x; i < lim; i += blockDim.x) {
        long long v = ei[i];
        if (v < 0 || v >= (long long)n) bad = 1;
    }
    __syncthreads();
    if (threadIdx.x == 0) g_is32 = bad;
}

// ---------------- CSR build ----------------
__global__ void k_prep(const void* __restrict__ ei, int E, int n) {
    int i = blockIdx.x * blockDim.x + threadIdx.x;
    if (i < E) {
        int s, d;
        if (g_is32) {
            const int* e32 = (const int*)ei;
            s = e32[i];
            d = e32[E + i];
        } else {
            const long long* e64 = (const long long*)ei;
            s = (int)e64[i];
            d = (int)e64[(size_t)E + i];
        }
        g_src[i] = s;
        g_dst[i] = d;
    }
    if (i < n) g_degi[i] = 0;
}

__global__ void k_deg(int E) {
    int e = blockIdx.x * blockDim.x + threadIdx.x;
    if (e < E) atomicAdd(&g_degi[g_dst[e]], 1);
}

// ---- 3-stage multi-block exclusive scan of g_degi -> g_off/g_cur ----
// Stage 1: per-block (1024 elems) local exclusive scan + block total + dis.
__global__ void k_scan_local(int n) {
    __shared__ int sh[1024];
    int t = threadIdx.x;
    int i = blockIdx.x * 1024 + t;
    int d = (i < n) ? g_degi[i] : 0;
    sh[t] = d;
    __syncthreads();
    for (int off = 1; off < 1024; off <<= 1) {
        int v = (t >= off) ? sh[t - off] : 0;
        __syncthreads();
        sh[t] += v;
        __syncthreads();
    }
    if (i < n) {
        g_off[i] = sh[t] - d;   // local exclusive prefix
        g_dis[i] = (d > 0) ? rsqrtf((float)d) : 0.0f;
    }
    if (t == 1023) g_bsum[blockIdx.x] = sh[1023];
}

// Stage 2: scan the block totals (nb <= 64), single tiny block.
__global__ void k_scan_bsum(int nb) {
    __shared__ int sh[NBMAX];
    int t = threadIdx.x;
    int d = (t < nb) ? g_bsum[t] : 0;
    sh[t] = d;
    __syncthreads();
    for (int off = 1; off < NBMAX; off <<= 1) {
        int v = (t >= off) ? sh[t - off] : 0;
        __syncthreads();
        sh[t] += v;
        __syncthreads();
    }
    if (t < nb) g_bsumex[t] = sh[t] - d;
}

// Stage 3: add block offsets; materialize off and cur.
__global__ void k_scan_add(int n) {
    int i = blockIdx.x * blockDim.x + threadIdx.x;
    if (i < n) {
        int o = g_off[i] + g_bsumex[i >> 10];
        g_off[i] = o;
        g_cur[i] = o;
    }
}

__global__ void k_fill(int E) {
    int e = blockIdx.x * blockDim.x + threadIdx.x;
    if (e < E) {
        int s = g_src[e], d = g_dst[e];
        int pos = atomicAdd(&g_cur[d], 1);
        float nm = g_dis[s] * g_dis[d];
        g_edge[pos] = make_int2(s, __float_as_int(nm));
    }
}

__global__ void k_cat(const float* __restrict__ wmu, const float* __restrict__ wls) {
    int i = blockIdx.x * blockDim.x + threadIdx.x;
    if (i < D * D) {
        int k = i >> 7, c = i & 127;
        g_Wcat[i] = (c < 64) ? wmu[k * 64 + c] : wls[k * 64 + (c - 64)];
    }
}

// ---------------- dense GEMM: OUT[n,128] = X[n,128] @ W[128,128] ----------------
// 256 threads, 128x128 block tile, 8x8 thread tile (cols strided by 16).
__global__ void __launch_bounds__(256, 2)
k_gemm(const float* __restrict__ X, const float* __restrict__ W,
       float* __restrict__ OUT, int nrows) {
    __shared__ float Ws[16][128];
    __shared__ float Xs[16][133];

    int tx = threadIdx.x;
    int c0 = tx & 15;            // cols c0 + 16*j, j=0..7
    int r0 = (tx >> 4) * 8;      // rows r0..r0+7
    int rowBase = blockIdx.x * 128;

    float acc[8][8];
#pragma unroll
    for (int i = 0; i < 8; i++)
#pragma unroll
        for (int j = 0; j < 8; j++) acc[i][j] = 0.0f;

    for (int kk = 0; kk < 128; kk += 16) {
        const float4* wg = (const float4*)(W + (size_t)kk * 128);
        float4* ws4 = (float4*)&Ws[0][0];
        ws4[tx] = wg[tx];
        ws4[tx + 256] = wg[tx + 256];

#pragma unroll
        for (int it = 0; it < 2; it++) {
            int idx = tx + it * 256;
            int row = idx >> 2;
            int k4  = idx & 3;
            int grow = rowBase + row;
            float4 v = (grow < nrows)
                       ? ((const float4*)(X + (size_t)grow * 128 + kk))[k4]
                       : make_float4(0.f, 0.f, 0.f, 0.f);
            Xs[k4 * 4 + 0][row] = v.x;
            Xs[k4 * 4 + 1][row] = v.y;
            Xs[k4 * 4 + 2][row] = v.z;
            Xs[k4 * 4 + 3][row] = v.w;
        }
        __syncthreads();

#pragma unroll
        for (int k = 0; k < 16; k++) {
            float xv[8], wv[8];
#pragma unroll
            for (int i = 0; i < 8; i++) xv[i] = Xs[k][r0 + i];
#pragma unroll
            for (int j = 0; j < 8; j++) wv[j] = Ws[k][c0 + 16 * j];
#pragma unroll
            for (int i = 0; i < 8; i++)
#pragma unroll
                for (int j = 0; j < 8; j++)
                    acc[i][j] += xv[i] * wv[j];
        }
        __syncthreads();
    }

#pragma unroll
    for (int i = 0; i < 8; i++) {
        int grow = rowBase + r0 + i;
        if (grow < nrows) {
            float* o = OUT + (size_t)grow * 128;
#pragma unroll
            for (int j = 0; j < 8; j++) o[c0 + 16 * j] = acc[i][j];
        }
    }
}

// ---------------- warp-per-node gather aggregation ----------------
__global__ void k_gather_relu(const float* __restrict__ h, float* __restrict__ out,
                              const float* __restrict__ b1, int n) {
    int w = (blockIdx.x * blockDim.x + threadIdx.x) >> 5;
    int lane = threadIdx.x & 31;
    if (w >= n) return;
    int start = g_off[w], deg = g_degi[w];
    float4 acc = make_float4(0.f, 0.f, 0.f, 0.f);
#pragma unroll 4
    for (int i = 0; i < deg; i++) {
        int2 ed = __ldg(&g_edge[start + i]);
        float nm = __int_as_float(ed.y);
        float4 v = ((const float4*)(h + (size_t)ed.x * 128))[lane];
        acc.x += nm * v.x; acc.y += nm * v.y;
        acc.z += nm * v.z; acc.w += nm * v.w;
    }
    float4 b = ((const float4*)b1)[lane];
    acc.x = fmaxf(acc.x + b.x, 0.f);
    acc.y = fmaxf(acc.y + b.y, 0.f);
    acc.z = fmaxf(acc.z + b.z, 0.f);
    acc.w = fmaxf(acc.w + b.w, 0.f);
    ((float4*)(out + (size_t)w * 128))[lane] = acc;
}

__global__ void k_gather_out(const float* __restrict__ h, float* __restrict__ out,
                             const float* __restrict__ bmu, const float* __restrict__ bls,
                             int half, int n) {
    int w = (blockIdx.x * blockDim.x + threadIdx.x) >> 5;
    int lane = threadIdx.x & 31;
    if (w >= n) return;
    int start = g_off[w], deg = g_degi[w];
    float4 acc = make_float4(0.f, 0.f, 0.f, 0.f);
#pragma unroll 4
    for (int i = 0; i < deg; i++) {
        int2 ed = __ldg(&g_edge[start + i]);
        float nm = __int_as_float(ed.y);
        float4 v = ((const float4*)(h + (size_t)ed.x * 128))[lane];
        acc.x += nm * v.x; acc.y += nm * v.y;
        acc.z += nm * v.z; acc.w += nm * v.w;
    }
    int col = lane * 4;
    float4 b; float* p;
    if (col < 64) {
        b = ((const float4*)bmu)[lane];
        p = out + (size_t)w * 64 + col;
    } else {
        b = ((const float4*)bls)[lane - 16];
        p = out + half + (size_t)w * 64 + (col - 64);
    }
    acc.x += b.x; acc.y += b.y; acc.z += b.z; acc.w += b.w;
    *(float4*)p = acc;
}

// ---------------- launch ----------------
extern "C" void kernel_launch(void* const* d_in, const int* in_sizes, int n_in,
                              void* d_out, int out_size) {
    const float* x   = (const float*)d_in[0];
    const void*  ei  = d_in[1];
    const float* w1  = (const float*)d_in[2];
    const float* b1  = (const float*)d_in[3];
    const float* wmu = (const float*)d_in[4];
    const float* bmu = (const float*)d_in[5];
    const float* wls = (const float*)d_in[6];
    const float* bls = (const float*)d_in[7];
    float* out = (float*)d_out;

    int n = in_sizes[0] / D;          // 50000
    int E = in_sizes[1] / 2;          // 800000
    int half = out_size / 2;          // n*64

    float *A, *B, *Wc;
    cudaGetSymbolAddress((void**)&A,  g_A);
    cudaGetSymbolAddress((void**)&B,  g_B);
    cudaGetSymbolAddress((void**)&Wc, g_Wcat);

    const int T = 256;
    int mEn = (E > n) ? E : n;
    int nb = (n + 1023) / 1024;

    // CSR build
    k_detect<<<1, 256>>>((const long long*)ei, E, n);
    k_prep<<<(mEn + T - 1) / T, T>>>(ei, E, n);
    k_deg<<<(E + T - 1) / T, T>>>(E);
    k_scan_local<<<nb, 1024>>>(n);
    k_scan_bsum<<<1, NBMAX>>>(nb);
    k_scan_add<<<(n + T - 1) / T, T>>>(n);
    k_fill<<<(E + T - 1) / T, T>>>(E);
    k_cat<<<(D * D + T - 1) / T, T>>>(wmu, wls);

    int gatherBlocks = (n * 32 + T - 1) / T;

    // layer 1: h_lin = x @ w1 ; h = relu(gather + b1)
    k_gemm<<<(n + 127) / 128, T>>>(x, w1, A, n);
    k_gather_relu<<<gatherBlocks, T>>>(A, B, b1, n);

    // layer 2 (fused mu|logstd): hm = h @ [w_mu|w_ls] ; out = gather + bias
    k_gemm<<<(n + 127) / 128, T>>>(B, Wc, A, n);
    k_gather_out<<<gatherBlocks, T>>>(A, out, bmu, bls, half, n);
}

// round 5
// speedup vs baseline: 1.5003x; 1.0290x over previous
#include <cuda_runtime.h>
#include <cstdint>

#define D    128
#define NMAX 50000
#define EMAX 800000
#define NBMAX 64   // ceil(NMAX/1024)=49

// ---------------- scratch (device globals: allocation-free) ----------------
__device__ __align__(16) float g_A[(size_t)NMAX * D];   // h_lin / hm
__device__ __align__(16) float g_B[(size_t)NMAX * D];   // h (post-relu)
__device__ __align__(16) float g_Wcat[D * D];           // [w_mu | w_ls]
__device__ int   g_degi[NMAX];
__device__ float g_dis[NMAX];
__device__ int   g_off[NMAX];
__device__ int   g_cur[NMAX];
__device__ int   g_bsum[NBMAX];
__device__ int   g_bsumex[NBMAX];
__device__ __align__(16) int2 g_edge[EMAX];             // (src, norm-as-int) CSR order
__device__ int   g_src[EMAX];
__device__ int   g_dst[EMAX];
__device__ int   g_is32;

// ---------------- edge-index dtype detection ----------------
__global__ void k_detect(const long long* __restrict__ ei, int total64, int n) {
    __shared__ int bad;
    if (threadIdx.x == 0) bad = 0;
    __syncthreads();
    int lim = total64 < 1024 ? total64 : 1024;
    for (int i = threadIdx.x; i < lim; i += blockDim.x) {
        long long v = ei[i];
        if (v < 0 || v >= (long long)n) bad = 1;
    }
    __syncthreads();
    if (threadIdx.x == 0) g_is32 = bad;
}

// ---------------- CSR build ----------------
__global__ void k_prep(const void* __restrict__ ei, int E, int n) {
    int i = blockIdx.x * blockDim.x + threadIdx.x;
    if (i < E) {
        int s, d;
        if (g_is32) {
            const int* e32 = (const int*)ei;
            s = e32[i];
            d = e32[E + i];
        } else {
            const long long* e64 = (const long long*)ei;
            s = (int)e64[i];
            d = (int)e64[(size_t)E + i];
        }
        g_src[i] = s;
        g_dst[i] = d;
    }
    if (i < n) g_degi[i] = 0;
}

__global__ void k_deg(int E) {
    int e = blockIdx.x * blockDim.x + threadIdx.x;
    if (e < E) atomicAdd(&g_degi[g_dst[e]], 1);
}

// ---- 3-stage multi-block exclusive scan of g_degi -> g_off/g_cur ----
__global__ void k_scan_local(int n) {
    __shared__ int sh[1024];
    int t = threadIdx.x;
    int i = blockIdx.x * 1024 + t;
    int d = (i < n) ? g_degi[i] : 0;
    sh[t] = d;
    __syncthreads();
    for (int off = 1; off < 1024; off <<= 1) {
        int v = (t >= off) ? sh[t - off] : 0;
        __syncthreads();
        sh[t] += v;
        __syncthreads();
    }
    if (i < n) {
        g_off[i] = sh[t] - d;
        g_dis[i] = (d > 0) ? rsqrtf((float)d) : 0.0f;
    }
    if (t == 1023) g_bsum[blockIdx.x] = sh[1023];
}

__global__ void k_scan_bsum(int nb) {
    __shared__ int sh[NBMAX];
    int t = threadIdx.x;
    int d = (t < nb) ? g_bsum[t] : 0;
    sh[t] = d;
    __syncthreads();
    for (int off = 1; off < NBMAX; off <<= 1) {
        int v = (t >= off) ? sh[t - off] : 0;
        __syncthreads();
        sh[t] += v;
        __syncthreads();
    }
    if (t < nb) g_bsumex[t] = sh[t] - d;
}

__global__ void k_scan_add(int n) {
    int i = blockIdx.x * blockDim.x + threadIdx.x;
    if (i < n) {
        int o = g_off[i] + g_bsumex[i >> 10];
        g_off[i] = o;
        g_cur[i] = o;
    }
}

__global__ void k_fill(int E) {
    int e = blockIdx.x * blockDim.x + threadIdx.x;
    if (e < E) {
        int s = g_src[e], d = g_dst[e];
        int pos = atomicAdd(&g_cur[d], 1);
        float nm = g_dis[s] * g_dis[d];
        g_edge[pos] = make_int2(s, __float_as_int(nm));
    }
}

__global__ void k_cat(const float* __restrict__ wmu, const float* __restrict__ wls) {
    int i = blockIdx.x * blockDim.x + threadIdx.x;
    if (i < D * D) {
        int k = i >> 7, c = i & 127;
        g_Wcat[i] = (c < 64) ? wmu[k * 64 + c] : wls[k * 64 + (c - 64)];
    }
}

// ---------------- 3xTF32 tensor-core GEMM ----------------
__device__ __forceinline__ float2 split_tf32(float x) {
    uint32_t hb;
    asm("cvt.rna.tf32.f32 %0, %1;" : "=r"(hb) : "f"(x));
    float h = __uint_as_float(hb);
    float l = x - h;
    uint32_t lb;
    asm("cvt.rna.tf32.f32 %0, %1;" : "=r"(lb) : "f"(l));
    return make_float2(h, __uint_as_float(lb));
}

__device__ __forceinline__ void mma_tf32(float* c, const uint32_t* a,
                                         uint32_t b0, uint32_t b1) {
    asm volatile(
        "mma.sync.aligned.m16n8k8.row.col.f32.tf32.tf32.f32 "
        "{%0,%1,%2,%3}, {%4,%5,%6,%7}, {%8,%9}, {%0,%1,%2,%3};"
        : "+f"(c[0]), "+f"(c[1]), "+f"(c[2]), "+f"(c[3])
        : "r"(a[0]), "r"(a[1]), "r"(a[2]), "r"(a[3]), "r"(b0), "r"(b1));
}

// OUT[n,128] = X[n,128] @ W[128,128]. 256 threads, 128x128 tile per block.
// Warp wp computes rows [16wp, 16wp+16), all 128 cols (16 n-tiles of 8).
__global__ void __launch_bounds__(256, 2)
k_gemm_tc(const float* __restrict__ X, const float* __restrict__ W,
          float* __restrict__ OUT, int nrows) {
    __shared__ float2 Ws[16][136];   // [k][n] (hi,lo); pad 136 -> conflict-free
    __shared__ float2 Xs[128][20];   // [row][k] (hi,lo); pad 20 -> conflict-free

    int tx = threadIdx.x;
    int lane = tx & 31, wp = tx >> 5;
    int g = lane >> 2, t = lane & 3;
    int rowBase = blockIdx.x * 128;
    int wr = wp * 16;

    float c[16][4];
#pragma unroll
    for (int j = 0; j < 16; j++) {
        c[j][0] = 0.f; c[j][1] = 0.f; c[j][2] = 0.f; c[j][3] = 0.f;
    }

    for (int kc = 0; kc < 8; kc++) {
        int k0 = kc * 16;
        // stage W chunk: rows k0..k0+15, 128 cols = 512 float4
#pragma unroll
        for (int i = 0; i < 2; i++) {
            int idx = tx + 256 * i;
            int k = idx >> 5, f4 = idx & 31;
            float4 v = ((const float4*)(W + (size_t)(k0 + k) * 128))[f4];
            Ws[k][f4 * 4 + 0] = split_tf32(v.x);
            Ws[k][f4 * 4 + 1] = split_tf32(v.y);
            Ws[k][f4 * 4 + 2] = split_tf32(v.z);
            Ws[k][f4 * 4 + 3] = split_tf32(v.w);
        }
        // stage X chunk: 128 rows x 16 cols = 512 float4
#pragma unroll
        for (int i = 0; i < 2; i++) {
            int idx = tx + 256 * i;
            int row = idx >> 2, f4 = idx & 3;
            int grow = rowBase + row;
            float4 v = (grow < nrows)
                       ? ((const float4*)(X + (size_t)grow * 128 + k0))[f4]
                       : make_float4(0.f, 0.f, 0.f, 0.f);
            Xs[row][f4 * 4 + 0] = split_tf32(v.x);
            Xs[row][f4 * 4 + 1] = split_tf32(v.y);
            Xs[row][f4 * 4 + 2] = split_tf32(v.z);
            Xs[row][f4 * 4 + 3] = split_tf32(v.w);
        }
        __syncthreads();

#pragma unroll
        for (int s = 0; s < 2; s++) {
            int kb = s * 8;
            float2 a0 = Xs[wr + g][kb + t];
            float2 a1 = Xs[wr + g + 8][kb + t];
            float2 a2 = Xs[wr + g][kb + t + 4];
            float2 a3 = Xs[wr + g + 8][kb + t + 4];
            uint32_t ah[4] = {__float_as_uint(a0.x), __float_as_uint(a1.x),
                              __float_as_uint(a2.x), __float_as_uint(a3.x)};
            uint32_t al[4] = {__float_as_uint(a0.y), __float_as_uint(a1.y),
                              __float_as_uint(a2.y), __float_as_uint(a3.y)};
#pragma unroll
            for (int j = 0; j < 16; j++) {
                float2 b0 = Ws[kb + t][j * 8 + g];
                float2 b1 = Ws[kb + t + 4][j * 8 + g];
                uint32_t bh0 = __float_as_uint(b0.x), bh1 = __float_as_uint(b1.x);
                uint32_t bl0 = __float_as_uint(b0.y), bl1 = __float_as_uint(b1.y);
                mma_tf32(c[j], ah, bh0, bh1);   // hi*hi
                mma_tf32(c[j], al, bh0, bh1);   // lo*hi
                mma_tf32(c[j], ah, bl0, bl1);   // hi*lo
            }
        }
        __syncthreads();
    }

    int r0 = rowBase + wr + g;
    int r1 = r0 + 8;
#pragma unroll
    for (int j = 0; j < 16; j++) {
        int col = j * 8 + 2 * t;
        if (r0 < nrows)
            *(float2*)(OUT + (size_t)r0 * 128 + col) = make_float2(c[j][0], c[j][1]);
        if (r1 < nrows)
            *(float2*)(OUT + (size_t)r1 * 128 + col) = make_float2(c[j][2], c[j][3]);
    }
}

// ---------------- warp-per-node gather aggregation ----------------
__global__ void k_gather_relu(const float* __restrict__ h, float* __restrict__ out,
                              const float* __restrict__ b1, int n) {
    int w = (blockIdx.x * blockDim.x + threadIdx.x) >> 5;
    int lane = threadIdx.x & 31;
    if (w >= n) return;
    int start = g_off[w], deg = g_degi[w];
    float4 acc = make_float4(0.f, 0.f, 0.f, 0.f);
#pragma unroll 4
    for (int i = 0; i < deg; i++) {
        int2 ed = __ldg(&g_edge[start + i]);
        float nm = __int_as_float(ed.y);
        float4 v = ((const float4*)(h + (size_t)ed.x * 128))[lane];
        acc.x += nm * v.x; acc.y += nm * v.y;
        acc.z += nm * v.z; acc.w += nm * v.w;
    }
    float4 b = ((const float4*)b1)[lane];
    acc.x = fmaxf(acc.x + b.x, 0.f);
    acc.y = fmaxf(acc.y + b.y, 0.f);
    acc.z = fmaxf(acc.z + b.z, 0.f);
    acc.w = fmaxf(acc.w + b.w, 0.f);
    ((float4*)(out + (size_t)w * 128))[lane] = acc;
}

__global__ void k_gather_out(const float* __restrict__ h, float* __restrict__ out,
                             const float* __restrict__ bmu, const float* __restrict__ bls,
                             int half, int n) {
    int w = (blockIdx.x * blockDim.x + threadIdx.x) >> 5;
    int lane = threadIdx.x & 31;
    if (w >= n) return;
    int start = g_off[w], deg = g_degi[w];
    float4 acc = make_float4(0.f, 0.f, 0.f, 0.f);
#pragma unroll 4
    for (int i = 0; i < deg; i++) {
        int2 ed = __ldg(&g_edge[start + i]);
        float nm = __int_as_float(ed.y);
        float4 v = ((const float4*)(h + (size_t)ed.x * 128))[lane];
        acc.x += nm * v.x; acc.y += nm * v.y;
        acc.z += nm * v.z; acc.w += nm * v.w;
    }
    int col = lane * 4;
    float4 b; float* p;
    if (col < 64) {
        b = ((const float4*)bmu)[lane];
        p = out + (size_t)w * 64 + col;
    } else {
        b = ((const float4*)bls)[lane - 16];
        p = out + half + (size_t)w * 64 + (col - 64);
    }
    acc.x += b.x; acc.y += b.y; acc.z += b.z; acc.w += b.w;
    *(float4*)p = acc;
}

// ---------------- launch ----------------
extern "C" void kernel_launch(void* const* d_in, const int* in_sizes, int n_in,
                              void* d_out, int out_size) {
    const float* x   = (const float*)d_in[0];
    const void*  ei  = d_in[1];
    const float* w1  = (const float*)d_in[2];
    const float* b1  = (const float*)d_in[3];
    const float* wmu = (const float*)d_in[4];
    const float* bmu = (const float*)d_in[5];
    const float* wls = (const float*)d_in[6];
    const float* bls = (const float*)d_in[7];
    float* out = (float*)d_out;

    int n = in_sizes[0] / D;          // 50000
    int E = in_sizes[1] / 2;          // 800000
    int half = out_size / 2;          // n*64

    float *A, *B, *Wc;
    cudaGetSymbolAddress((void**)&A,  g_A);
    cudaGetSymbolAddress((void**)&B,  g_B);
    cudaGetSymbolAddress((void**)&Wc, g_Wcat);

    const int T = 256;
    int mEn = (E > n) ? E : n;
    int nb = (n + 1023) / 1024;

    // CSR build
    k_detect<<<1, 256>>>((const long long*)ei, E, n);
    k_prep<<<(mEn + T - 1) / T, T>>>(ei, E, n);
    k_deg<<<(E + T - 1) / T, T>>>(E);
    k_scan_local<<<nb, 1024>>>(n);
    k_scan_bsum<<<1, NBMAX>>>(nb);
    k_scan_add<<<(n + T - 1) / T, T>>>(n);
    k_fill<<<(E + T - 1) / T, T>>>(E);
    k_cat<<<(D * D + T - 1) / T, T>>>(wmu, wls);

    int gatherBlocks = (n * 32 + T - 1) / T;
    int gemmBlocks = (n + 127) / 128;

    // layer 1: h_lin = x @ w1 ; h = relu(gather + b1)
    k_gemm_tc<<<gemmBlocks, T>>>(x, w1, A, n);
    k_gather_relu<<<gatherBlocks, T>>>(A, B, b1, n);

    // layer 2 (fused mu|logstd): hm = h @ [w_mu|w_ls] ; out = gather + bias
    k_gemm_tc<<<gemmBlocks, T>>>(B, Wc, A, n);
    k_gather_out<<<gatherBlocks, T>>>(A, out, bmu, bls, half, n);
}

// round 7
// speedup vs baseline: 1.6643x; 1.1093x over previous
#include <cuda_runtime.h>
#include <cuda_fp16.h>
#include <cstdint>

#define D    128
#define NMAX 50000
#define EMAX 800000
#define NBMAX 64   // ceil(NMAX/1024)=49

// ---------------- scratch (device globals: allocation-free) ----------------
__device__ __align__(16) __half g_Ah[(size_t)NMAX * D];   // h_lin / hm (fp16)
__device__ __align__(16) __half g_Bh[(size_t)NMAX * D];   // h post-relu (fp16)
__device__ __align__(16) float  g_Wcat[D * D];            // [w_mu | w_ls]
__device__ int   g_degi[NMAX];
__device__ float g_dis[NMAX];
__device__ int   g_off[NMAX];
__device__ int   g_cur[NMAX];
__device__ int   g_bsum[NBMAX];
__device__ int   g_bsumex[NBMAX];
__device__ __align__(16) int2 g_edge[EMAX];               // (src, norm-as-int) CSR order
__device__ int   g_is32;

// ---------------- edge-index dtype detection ----------------
__global__ void k_detect(const long long* __restrict__ ei, int total64, int n) {
    __shared__ int bad;
    if (threadIdx.x == 0) bad = 0;
    __syncthreads();
    int lim = total64 < 1024 ? total64 : 1024;
    for (int i = threadIdx.x; i < lim; i += blockDim.x) {
        long long v = ei[i];
        if (v < 0 || v >= (long long)n) bad = 1;
    }
    __syncthreads();
    if (threadIdx.x == 0) g_is32 = bad;
}

// ---------------- CSR build ----------------
__global__ void k_zero_deg(int n) {
    int i = blockIdx.x * blockDim.x + threadIdx.x;
    if (i < n) g_degi[i] = 0;
}

// decode dst straight from edge_index, histogram degrees
__global__ void k_deg(const void* __restrict__ ei, int E) {
    int i = blockIdx.x * blockDim.x + threadIdx.x;
    if (i < E) {
        int d = g_is32 ? ((const int*)ei)[E + i]
                       : (int)((const long long*)ei)[(size_t)E + i];
        atomicAdd(&g_degi[d], 1);
    }
}

// ---- 3-stage multi-block exclusive scan of g_degi -> g_off/g_cur ----
__global__ void k_scan_local(int n) {
    __shared__ int sh[1024];
    int t = threadIdx.x;
    int i = blockIdx.x * 1024 + t;
    int d = (i < n) ? g_degi[i] : 0;
    sh[t] = d;
    __syncthreads();
    for (int off = 1; off < 1024; off <<= 1) {
        int v = (t >= off) ? sh[t - off] : 0;
        __syncthreads();
        sh[t] += v;
        __syncthreads();
    }
    if (i < n) {
        g_off[i] = sh[t] - d;
        g_dis[i] = (d > 0) ? rsqrtf((float)d) : 0.0f;
    }
    if (t == 1023) g_bsum[blockIdx.x] = sh[1023];
}

__global__ void k_scan_bsum(int nb) {
    __shared__ int sh[NBMAX];
    int t = threadIdx.x;
    int d = (t < nb) ? g_bsum[t] : 0;
    sh[t] = d;
    __syncthreads();
    for (int off = 1; off < NBMAX; off <<= 1) {
        int v = (t >= off) ? sh[t - off] : 0;
        __syncthreads();
        sh[t] += v;
        __syncthreads();
    }
    if (t < nb) g_bsumex[t] = sh[t] - d;
}

__global__ void k_scan_add(int n) {
    int i = blockIdx.x * blockDim.x + threadIdx.x;
    if (i < n) {
        int o = g_off[i] + g_bsumex[i >> 10];
        g_off[i] = o;
        g_cur[i] = o;
    }
}

// decode (src,dst), compute norm, place edge at CSR cursor
__global__ void k_fill(const void* __restrict__ ei, int E) {
    int i = blockIdx.x * blockDim.x + threadIdx.x;
    if (i < E) {
        int s, d;
        if (g_is32) {
            const int* p = (const int*)ei;
            s = p[i]; d = p[E + i];
        } else {
            const long long* p = (const long long*)ei;
            s = (int)p[i]; d = (int)p[(size_t)E + i];
        }
        int pos = atomicAdd(&g_cur[d], 1);
        g_edge[pos] = make_int2(s, __float_as_int(g_dis[s] * g_dis[d]));
    }
}

__global__ void k_cat(const float* __restrict__ wmu, const float* __restrict__ wls) {
    int i = blockIdx.x * blockDim.x + threadIdx.x;
    if (i < D * D) {
        int k = i >> 7, c = i & 127;
        g_Wcat[i] = (c < 64) ? wmu[k * 64 + c] : wls[k * 64 + (c - 64)];
    }
}

// ---------------- 3xTF32 tensor-core GEMM (fp32 or fp16 input, fp16 output) ----------------
__device__ __forceinline__ float2 split_tf32(float x) {
    uint32_t hb;
    asm("cvt.rna.tf32.f32 %0, %1;" : "=r"(hb) : "f"(x));
    float h = __uint_as_float(hb);
    float l = x - h;
    uint32_t lb;
    asm("cvt.rna.tf32.f32 %0, %1;" : "=r"(lb) : "f"(l));
    return make_float2(h, __uint_as_float(lb));
}

__device__ __forceinline__ void mma_tf32(float* c, const uint32_t* a,
                                         uint32_t b0, uint32_t b1) {
    asm volatile(
        "mma.sync.aligned.m16n8k8.row.col.f32.tf32.tf32.f32 "
        "{%0,%1,%2,%3}, {%4,%5,%6,%7}, {%8,%9}, {%0,%1,%2,%3};"
        : "+f"(c[0]), "+f"(c[1]), "+f"(c[2]), "+f"(c[3])
        : "r"(a[0]), "r"(a[1]), "r"(a[2]), "r"(a[3]), "r"(b0), "r"(b1));
}

__device__ __forceinline__ float4 ld4(const float* p, int f4) {
    return ((const float4*)p)[f4];
}
__device__ __forceinline__ float4 ld4(const __half* p, int f4) {
    uint2 u = ((const uint2*)p)[f4];
    float2 a = __half22float2(*(__half2*)&u.x);
    float2 b = __half22float2(*(__half2*)&u.y);
    return make_float4(a.x, a.y, b.x, b.y);
}

// OUT[n,128] = X[n,128] @ W[128,128]. 256 threads, 128x128 tile per block.
template <typename IT>
__global__ void __launch_bounds__(256, 2)
k_gemm_tc(const IT* __restrict__ X, const float* __restrict__ W,
          __half* __restrict__ OUT, int nrows) {
    __shared__ float2 Ws[16][136];   // [k][n] (hi,lo)
    __shared__ float2 Xs[128][20];   // [row][k] (hi,lo)

    int tx = threadIdx.x;
    int lane = tx & 31, wp = tx >> 5;
    int g = lane >> 2, t = lane & 3;
    int rowBase = blockIdx.x * 128;
    int wr = wp * 16;

    float c[16][4];
#pragma unroll
    for (int j = 0; j < 16; j++) {
        c[j][0] = 0.f; c[j][1] = 0.f; c[j][2] = 0.f; c[j][3] = 0.f;
    }

    for (int kc = 0; kc < 8; kc++) {
        int k0 = kc * 16;
#pragma unroll
        for (int i = 0; i < 2; i++) {
            int idx = tx + 256 * i;
            int k = idx >> 5, f4 = idx & 31;
            float4 v = ld4(W + (size_t)(k0 + k) * 128, f4);
            Ws[k][f4 * 4 + 0] = split_tf32(v.x);
            Ws[k][f4 * 4 + 1] = split_tf32(v.y);
            Ws[k][f4 * 4 + 2] = split_tf32(v.z);
            Ws[k][f4 * 4 + 3] = split_tf32(v.w);
        }
#pragma unroll
        for (int i = 0; i < 2; i++) {
            int idx = tx + 256 * i;
            int row = idx >> 2, f4 = idx & 3;
            int grow = rowBase + row;
            float4 v = (grow < nrows)
                       ? ld4(X + (size_t)grow * 128 + k0, f4)
                       : make_float4(0.f, 0.f, 0.f, 0.f);
            Xs[row][f4 * 4 + 0] = split_tf32(v.x);
            Xs[row][f4 * 4 + 1] = split_tf32(v.y);
            Xs[row][f4 * 4 + 2] = split_tf32(v.z);
            Xs[row][f4 * 4 + 3] = split_tf32(v.w);
        }
        __syncthreads();

#pragma unroll
        for (int s = 0; s < 2; s++) {
            int kb = s * 8;
            float2 a0 = Xs[wr + g][kb + t];
            float2 a1 = Xs[wr + g + 8][kb + t];
            float2 a2 = Xs[wr + g][kb + t + 4];
            float2 a3 = Xs[wr + g + 8][kb + t + 4];
            uint32_t ah[4] = {__float_as_uint(a0.x), __float_as_uint(a1.x),
                              __float_as_uint(a2.x), __float_as_uint(a3.x)};
            uint32_t al[4] = {__float_as_uint(a0.y), __float_as_uint(a1.y),
                              __float_as_uint(a2.y), __float_as_uint(a3.y)};
#pragma unroll
            for (int j = 0; j < 16; j++) {
                float2 b0 = Ws[kb + t][j * 8 + g];
                float2 b1 = Ws[kb + t + 4][j * 8 + g];
                uint32_t bh0 = __float_as_uint(b0.x), bh1 = __float_as_uint(b1.x);
                uint32_t bl0 = __float_as_uint(b0.y), bl1 = __float_as_uint(b1.y);
                mma_tf32(c[j], ah, bh0, bh1);   // hi*hi
                mma_tf32(c[j], al, bh0, bh1);   // lo*hi
                mma_tf32(c[j], ah, bl0, bl1);   // hi*lo
            }
        }
        __syncthreads();
    }

    int r0 = rowBase + wr + g;
    int r1 = r0 + 8;
#pragma unroll
    for (int j = 0; j < 16; j++) {
        int col = j * 8 + 2 * t;
        if (r0 < nrows)
            *(__half2*)(OUT + (size_t)r0 * 128 + col) = __floats2half2_rn(c[j][0], c[j][1]);
        if (r1 < nrows)
            *(__half2*)(OUT + (size_t)r1 * 128 + col) = __floats2half2_rn(c[j][2], c[j][3]);
    }
}

// ---------------- warp-per-node gather aggregation (fp16 rows) ----------------
// Layer 1: h = relu(sum(norm*h_lin[src]) + b1), fp16 in, fp16 out.
__global__ void k_gather_relu(const __half* __restrict__ h, __half* __restrict__ out,
                              const float* __restrict__ b1, int n) {
    int w = (blockIdx.x * blockDim.x + threadIdx.x) >> 5;
    int lane = threadIdx.x & 31;
    if (w >= n) return;
    int start = g_off[w], deg = g_degi[w];
    float4 acc = make_float4(0.f, 0.f, 0.f, 0.f);
#pragma unroll 4
    for (int i = 0; i < deg; i++) {
        int2 ed = __ldg(&g_edge[start + i]);
        float nm = __int_as_float(ed.y);
        uint2 u = ((const uint2*)(h + (size_t)ed.x * 128))[lane];
        float2 v0 = __half22float2(*(__half2*)&u.x);
        float2 v1 = __half22float2(*(__half2*)&u.y);
        acc.x += nm * v0.x; acc.y += nm * v0.y;
        acc.z += nm * v1.x; acc.w += nm * v1.y;
    }
    float4 b = ((const float4*)b1)[lane];
    acc.x = fmaxf(acc.x + b.x, 0.f);
    acc.y = fmaxf(acc.y + b.y, 0.f);
    acc.z = fmaxf(acc.z + b.z, 0.f);
    acc.w = fmaxf(acc.w + b.w, 0.f);
    uint2 o;
    *(__half2*)&o.x = __floats2half2_rn(acc.x, acc.y);
    *(__half2*)&o.y = __floats2half2_rn(acc.z, acc.w);
    ((uint2*)(out + (size_t)w * 128))[lane] = o;
}

// Layer 2: fp16 hm in, fp32 split mu|logstd out with fused bias.
__global__ void k_gather_out(const __half* __restrict__ h, float* __restrict__ out,
                             const float* __restrict__ bmu, const float* __restrict__ bls,
                             int half, int n) {
    int w = (blockIdx.x * blockDim.x + threadIdx.x) >> 5;
    int lane = threadIdx.x & 31;
    if (w >= n) return;
    int start = g_off[w], deg = g_degi[w];
    float4 acc = make_float4(0.f, 0.f, 0.f, 0.f);
#pragma unroll 4
    for (int i = 0; i < deg; i++) {
        int2 ed = __ldg(&g_edge[start + i]);
        float nm = __int_as_float(ed.y);
        uint2 u = ((const uint2*)(h + (size_t)ed.x * 128))[lane];
        float2 v0 = __half22float2(*(__half2*)&u.x);
        float2 v1 = __half22float2(*(__half2*)&u.y);
        acc.x += nm * v0.x; acc.y += nm * v0.y;
        acc.z += nm * v1.x; acc.w += nm * v1.y;
    }
    int col = lane * 4;
    float4 b; float* p;
    if (col < 64) {
        b = ((const float4*)bmu)[lane];
        p = out + (size_t)w * 64 + col;
    } else {
        b = ((const float4*)bls)[lane - 16];
        p = out + half + (size_t)w * 64 + (col - 64);
    }
    acc.x += b.x; acc.y += b.y; acc.z += b.z; acc.w += b.w;
    *(float4*)p = acc;
}

// ---------------- launch ----------------
extern "C" void kernel_launch(void* const* d_in, const int* in_sizes, int n_in,
                              void* d_out, int out_size) {
    const float* x   = (const float*)d_in[0];
    const void*  ei  = d_in[1];
    const float* w1  = (const float*)d_in[2];
    const float* b1  = (const float*)d_in[3];
    const float* wmu = (const float*)d_in[4];
    const float* bmu = (const float*)d_in[5];
    const float* wls = (const float*)d_in[6];
    const float* bls = (const float*)d_in[7];
    float* out = (float*)d_out;

    int n = in_sizes[0] / D;          // 50000
    int E = in_sizes[1] / 2;          // 800000
    int half = out_size / 2;          // n*64

    __half *Ah, *Bh;
    float *Wc;
    cudaGetSymbolAddress((void**)&Ah, g_Ah);
    cudaGetSymbolAddress((void**)&Bh, g_Bh);
    cudaGetSymbolAddress((void**)&Wc, g_Wcat);

    const int T = 256;
    int nb = (n + 1023) / 1024;

    // CSR build
    k_detect<<<1, 256>>>((const long long*)ei, E, n);
    k_zero_deg<<<(n + T - 1) / T, T>>>(n);
    k_deg<<<(E + T - 1) / T, T>>>(ei, E);
    k_scan_local<<<nb, 1024>>>(n);
    k_scan_bsum<<<1, NBMAX>>>(nb);
    k_scan_add<<<(n + T - 1) / T, T>>>(n);
    k_fill<<<(E + T - 1) / T, T>>>(ei, E);
    k_cat<<<(D * D + T - 1) / T, T>>>(wmu, wls);

    int gatherBlocks = (n * 32 + T - 1) / T;
    int gemmBlocks = (n + 127) / 128;

    // layer 1: h_lin = x @ w1 (fp16 out) ; h = relu(gather + b1) (fp16)
    k_gemm_tc<float><<<gemmBlocks, T>>>(x, w1, Ah, n);
    k_gather_relu<<<gatherBlocks, T>>>(Ah, Bh, b1, n);

    // layer 2 (fused mu|logstd): hm = h @ [w_mu|w_ls] (fp16) ; out = gather + bias
    k_gemm_tc<__half><<<gemmBlocks, T>>>(Bh, Wc, Ah, n);
    k_gather_out<<<gatherBlocks, T>>>(Ah, out, bmu, bls, half, n);
}

// round 8
// speedup vs baseline: 2.3212x; 1.3947x over previous
#include <cuda_runtime.h>
#include <cuda_fp16.h>
#include <cstdint>

#define D    128
#define NMAX 50000
#define EMAX 800000
#define NBMAX 64   // ceil(NMAX/1024)=49

// ---------------- scratch (device globals: allocation-free) ----------------
__device__ __align__(16) __half g_Ah[(size_t)NMAX * D];   // h_lin' / hm' (fp16, dis-scaled)
__device__ __align__(16) __half g_Bh[(size_t)NMAX * D];   // h post-relu (fp16)
__device__ __align__(16) float  g_Wcat[D * D];            // [w_mu | w_ls]
__device__ int   g_degi[NMAX];
__device__ float g_dis[NMAX];
__device__ int   g_off[NMAX];
__device__ int   g_cur[NMAX];
__device__ int   g_bsum[NBMAX];
__device__ int   g_bsumex[NBMAX];
__device__ int   g_eidx[EMAX];    // CSR-ordered src indices (norm factored out)
__device__ int   g_is32;

// ---------------- init: zero degrees + edge-index dtype detection ----------------
__global__ void k_init(const long long* __restrict__ ei, int E, int n) {
    int i = blockIdx.x * blockDim.x + threadIdx.x;
    if (i < n) g_degi[i] = 0;
    if (blockIdx.x == 0) {
        __shared__ int bad;
        if (threadIdx.x == 0) bad = 0;
        __syncthreads();
        int lim = E < 1024 ? E : 1024;
        for (int k = threadIdx.x; k < lim; k += blockDim.x) {
            long long v = ei[k];
            if (v < 0 || v >= (long long)n) bad = 1;
        }
        __syncthreads();
        if (threadIdx.x == 0) g_is32 = bad;
    }
}

// decode dst straight from edge_index, histogram degrees
__global__ void k_deg(const void* __restrict__ ei, int E) {
    int i = blockIdx.x * blockDim.x + threadIdx.x;
    if (i < E) {
        int d = g_is32 ? ((const int*)ei)[E + i]
                       : (int)((const long long*)ei)[(size_t)E + i];
        atomicAdd(&g_degi[d], 1);
    }
}

// ---- 3-stage multi-block exclusive scan of g_degi -> g_off/g_cur ----
__global__ void k_scan_local(int n) {
    __shared__ int sh[1024];
    int t = threadIdx.x;
    int i = blockIdx.x * 1024 + t;
    int d = (i < n) ? g_degi[i] : 0;
    sh[t] = d;
    __syncthreads();
    for (int off = 1; off < 1024; off <<= 1) {
        int v = (t >= off) ? sh[t - off] : 0;
        __syncthreads();
        sh[t] += v;
        __syncthreads();
    }
    if (i < n) {
        g_off[i] = sh[t] - d;
        g_dis[i] = (d > 0) ? rsqrtf((float)d) : 0.0f;
    }
    if (t == 1023) g_bsum[blockIdx.x] = sh[1023];
}

__global__ void k_scan_bsum(int nb) {
    __shared__ int sh[NBMAX];
    int t = threadIdx.x;
    int d = (t < nb) ? g_bsum[t] : 0;
    sh[t] = d;
    __syncthreads();
    for (int off = 1; off < NBMAX; off <<= 1) {
        int v = (t >= off) ? sh[t - off] : 0;
        __syncthreads();
        sh[t] += v;
        __syncthreads();
    }
    if (t < nb) g_bsumex[t] = sh[t] - d;
}

__global__ void k_scan_add(int n) {
    int i = blockIdx.x * blockDim.x + threadIdx.x;
    if (i < n) {
        int o = g_off[i] + g_bsumex[i >> 10];
        g_off[i] = o;
        g_cur[i] = o;
    }
}

// decode (src,dst), place src at CSR cursor (no norm needed)
__global__ void k_fill(const void* __restrict__ ei, int E) {
    int i = blockIdx.x * blockDim.x + threadIdx.x;
    if (i < E) {
        int s, d;
        if (g_is32) {
            const int* p = (const int*)ei;
            s = p[i]; d = p[E + i];
        } else {
            const long long* p = (const long long*)ei;
            s = (int)p[i]; d = (int)p[(size_t)E + i];
        }
        int pos = atomicAdd(&g_cur[d], 1);
        g_eidx[pos] = s;
    }
}

__global__ void k_cat(const float* __restrict__ wmu, const float* __restrict__ wls) {
    int i = blockIdx.x * blockDim.x + threadIdx.x;
    if (i < D * D) {
        int k = i >> 7, c = i & 127;
        g_Wcat[i] = (c < 64) ? wmu[k * 64 + c] : wls[k * 64 + (c - 64)];
    }
}

// ---------------- fp16 tensor-core GEMM with W error-split ----------------
// OUT[r,:] = dis[r] * (X[r,:] @ W), fp16 out.
// PASSES==2: X fp16 (exact A). PASSES==3: X fp32, split into fp16 hi+lo.
__device__ __forceinline__ void mma_f16(float* c, const uint32_t* a,
                                        uint32_t b0, uint32_t b1) {
    asm volatile(
        "mma.sync.aligned.m16n8k16.row.col.f32.f16.f16.f32 "
        "{%0,%1,%2,%3}, {%4,%5,%6,%7}, {%8,%9}, {%0,%1,%2,%3};"
        : "+f"(c[0]), "+f"(c[1]), "+f"(c[2]), "+f"(c[3])
        : "r"(a[0]), "r"(a[1]), "r"(a[2]), "r"(a[3]), "r"(b0), "r"(b1));
}

template <int PASSES, typename IT>
__global__ void __launch_bounds__(256, 2)
k_gemm_f16(const IT* __restrict__ X, const float* __restrict__ W,
           __half* __restrict__ OUT, int nrows) {
    // Bs[p][n][kp]: half2 = (W[2kp][n], W[2kp+1][n]); p=0 hi, p=1 lo
    __shared__ __half2 Bs[2][128][9];
    // As[p][row][kp]: half2 = (X[row][2kp], X[row][2kp+1])
    __shared__ __half2 As[(PASSES == 3) ? 2 : 1][128][9];

    int tx = threadIdx.x;
    int lane = tx & 31, wp = tx >> 5;
    int g = lane >> 2, t = lane & 3;
    int rowBase = blockIdx.x * 128;
    int wr = wp * 16;

    float c[16][4];
#pragma unroll
    for (int j = 0; j < 16; j++) {
        c[j][0] = 0.f; c[j][1] = 0.f; c[j][2] = 0.f; c[j][3] = 0.f;
    }

    for (int kc = 0; kc < 8; kc++) {
        int k0 = kc * 16;
        // stage W: 8 k-pairs x 128 n = 1024 entries, hi+lo split
#pragma unroll
        for (int it = 0; it < 4; it++) {
            int q = tx + it * 256;
            int n = q & 127, kp = q >> 7;
            float w0 = W[(size_t)(k0 + 2 * kp) * 128 + n];
            float w1 = W[(size_t)(k0 + 2 * kp + 1) * 128 + n];
            __half h0 = __float2half_rn(w0), h1 = __float2half_rn(w1);
            Bs[0][n][kp] = __halves2half2(h0, h1);
            Bs[1][n][kp] = __halves2half2(
                __float2half_rn(w0 - __half2float(h0)),
                __float2half_rn(w1 - __half2float(h1)));
        }
        // stage X: 128 rows x 16 k
#pragma unroll
        for (int it = 0; it < 2; it++) {
            int q = tx + it * 256;
            int row = q >> 2, j4 = q & 3;
            int grow = rowBase + row;
            if (PASSES == 2) {
                uint2 u = (grow < nrows)
                          ? ((const uint2*)((const __half*)X + (size_t)grow * 128 + k0))[j4]
                          : make_uint2(0u, 0u);
                As[0][row][j4 * 2 + 0] = *(__half2*)&u.x;
                As[0][row][j4 * 2 + 1] = *(__half2*)&u.y;
            } else {
                float4 v = (grow < nrows)
                           ? ((const float4*)((const float*)X + (size_t)grow * 128 + k0))[j4]
                           : make_float4(0.f, 0.f, 0.f, 0.f);
                __half hx = __float2half_rn(v.x), hy = __float2half_rn(v.y);
                __half hz = __float2half_rn(v.z), hw = __float2half_rn(v.w);
                As[0][row][j4 * 2 + 0] = __halves2half2(hx, hy);
                As[0][row][j4 * 2 + 1] = __halves2half2(hz, hw);
                As[PASSES == 3 ? 1 : 0][row][j4 * 2 + 0] = __halves2half2(
                    __float2half_rn(v.x - __half2float(hx)),
                    __float2half_rn(v.y - __half2float(hy)));
                As[PASSES == 3 ? 1 : 0][row][j4 * 2 + 1] = __halves2half2(
                    __float2half_rn(v.z - __half2float(hz)),
                    __float2half_rn(v.w - __half2float(hw)));
            }
        }
        __syncthreads();

        uint32_t A0[4], A1[4];
        A0[0] = *(uint32_t*)&As[0][wr + g][t];
        A0[1] = *(uint32_t*)&As[0][wr + g + 8][t];
        A0[2] = *(uint32_t*)&As[0][wr + g][t + 4];
        A0[3] = *(uint32_t*)&As[0][wr + g + 8][t + 4];
        if (PASSES == 3) {
            A1[0] = *(uint32_t*)&As[1][wr + g][t];
            A1[1] = *(uint32_t*)&As[1][wr + g + 8][t];
            A1[2] = *(uint32_t*)&As[1][wr + g][t + 4];
            A1[3] = *(uint32_t*)&As[1][wr + g + 8][t + 4];
        }
#pragma unroll
        for (int j = 0; j < 16; j++) {
            uint32_t bh0 = *(uint32_t*)&Bs[0][j * 8 + g][t];
            uint32_t bh1 = *(uint32_t*)&Bs[0][j * 8 + g][t + 4];
            uint32_t bl0 = *(uint32_t*)&Bs[1][j * 8 + g][t];
            uint32_t bl1 = *(uint32_t*)&Bs[1][j * 8 + g][t + 4];
            mma_f16(c[j], A0, bh0, bh1);            // Xh * Wh
            if (PASSES == 3) mma_f16(c[j], A1, bh0, bh1);  // Xl * Wh
            mma_f16(c[j], A0, bl0, bl1);            // Xh * Wl
        }
        __syncthreads();
    }

    int r0 = rowBase + wr + g;
    int r1 = r0 + 8;
    float d0 = (r0 < nrows) ? g_dis[r0] : 0.f;
    float d1 = (r1 < nrows) ? g_dis[r1] : 0.f;
#pragma unroll
    for (int j = 0; j < 16; j++) {
        int col = j * 8 + 2 * t;
        if (r0 < nrows)
            *(__half2*)(OUT + (size_t)r0 * 128 + col) =
                __floats2half2_rn(c[j][0] * d0, c[j][1] * d0);
        if (r1 < nrows)
            *(__half2*)(OUT + (size_t)r1 * 128 + col) =
                __floats2half2_rn(c[j][2] * d1, c[j][3] * d1);
    }
}

// ---------------- warp-per-node gather aggregation (norm factored) ----------------
// Layer 1: h = relu(dis[w] * sum(h'[src]) + b1), fp16 in/out.
__global__ void k_gather_relu(const __half* __restrict__ h, __half* __restrict__ out,
                              const float* __restrict__ b1, int n) {
    int w = (blockIdx.x * blockDim.x + threadIdx.x) >> 5;
    int lane = threadIdx.x & 31;
    if (w >= n) return;
    int start = g_off[w], deg = g_degi[w];
    float4 acc = make_float4(0.f, 0.f, 0.f, 0.f);
#pragma unroll 4
    for (int i = 0; i < deg; i++) {
        int s = __ldg(&g_eidx[start + i]);
        uint2 u = ((const uint2*)(h + (size_t)s * 128))[lane];
        float2 v0 = __half22float2(*(__half2*)&u.x);
        float2 v1 = __half22float2(*(__half2*)&u.y);
        acc.x += v0.x; acc.y += v0.y;
        acc.z += v1.x; acc.w += v1.y;
    }
    float dw = g_dis[w];
    float4 b = ((const float4*)b1)[lane];
    acc.x = fmaxf(acc.x * dw + b.x, 0.f);
    acc.y = fmaxf(acc.y * dw + b.y, 0.f);
    acc.z = fmaxf(acc.z * dw + b.z, 0.f);
    acc.w = fmaxf(acc.w * dw + b.w, 0.f);
    uint2 o;
    *(__half2*)&o.x = __floats2half2_rn(acc.x, acc.y);
    *(__half2*)&o.y = __floats2half2_rn(acc.z, acc.w);
    ((uint2*)(out + (size_t)w * 128))[lane] = o;
}

// Layer 2: fp16 hm' in, fp32 split mu|logstd out with fused bias.
__global__ void k_gather_out(const __half* __restrict__ h, float* __restrict__ out,
                             const float* __restrict__ bmu, const float* __restrict__ bls,
                             int half, int n) {
    int w = (blockIdx.x * blockDim.x + threadIdx.x) >> 5;
    int lane = threadIdx.x & 31;
    if (w >= n) return;
    int start = g_off[w], deg = g_degi[w];
    float4 acc = make_float4(0.f, 0.f, 0.f, 0.f);
#pragma unroll 4
    for (int i = 0; i < deg; i++) {
        int s = __ldg(&g_eidx[start + i]);
        uint2 u = ((const uint2*)(h + (size_t)s * 128))[lane];
        float2 v0 = __half22float2(*(__half2*)&u.x);
        float2 v1 = __half22float2(*(__half2*)&u.y);
        acc.x += v0.x; acc.y += v0.y;
        acc.z += v1.x; acc.w += v1.y;
    }
    float dw = g_dis[w];
    int col = lane * 4;
    float4 b; float* p;
    if (col < 64) {
        b = ((const float4*)bmu)[lane];
        p = out + (size_t)w * 64 + col;
    } else {
        b = ((const float4*)bls)[lane - 16];
        p = out + half + (size_t)w * 64 + (col - 64);
    }
    acc.x = acc.x * dw + b.x; acc.y = acc.y * dw + b.y;
    acc.z = acc.z * dw + b.z; acc.w = acc.w * dw + b.w;
    *(float4*)p = acc;
}

// ---------------- launch ----------------
extern "C" void kernel_launch(void* const* d_in, const int* in_sizes, int n_in,
                              void* d_out, int out_size) {
    const float* x   = (const float*)d_in[0];
    const void*  ei  = d_in[1];
    const float* w1  = (const float*)d_in[2];
    const float* b1  = (const float*)d_in[3];
    const float* wmu = (const float*)d_in[4];
    const float* bmu = (const float*)d_in[5];
    const float* wls = (const float*)d_in[6];
    const float* bls = (const float*)d_in[7];
    float* out = (float*)d_out;

    int n = in_sizes[0] / D;          // 50000
    int E = in_sizes[1] / 2;          // 800000
    int half = out_size / 2;          // n*64

    __half *Ah, *Bh;
    float *Wc;
    cudaGetSymbolAddress((void**)&Ah, g_Ah);
    cudaGetSymbolAddress((void**)&Bh, g_Bh);
    cudaGetSymbolAddress((void**)&Wc, g_Wcat);

    const int T = 256;
    int nb = (n + 1023) / 1024;

    // CSR build
    k_init<<<(n + T - 1) / T, T>>>((const long long*)ei, E, n);
    k_deg<<<(E + T - 1) / T, T>>>(ei, E);
    k_scan_local<<<nb, 1024>>>(n);
    k_scan_bsum<<<1, NBMAX>>>(nb);
    k_scan_add<<<(n + T - 1) / T, T>>>(n);
    k_fill<<<(E + T - 1) / T, T>>>(ei, E);
    k_cat<<<(D * D + T - 1) / T, T>>>(wmu, wls);

    int gatherBlocks = (n * 32 + T - 1) / T;
    int gemmBlocks = (n + 127) / 128;

    // layer 1: h_lin' = dis .* (x @ w1) ; h = relu(dis*gather + b1)
    k_gemm_f16<3, float><<<gemmBlocks, T>>>(x, w1, Ah, n);
    k_gather_relu<<<gatherBlocks, T>>>(Ah, Bh, b1, n);

    // layer 2 (fused mu|logstd): hm' = dis .* (h @ [w_mu|w_ls]) ; out = dis*gather + bias
    k_gemm_f16<2, __half><<<gemmBlocks, T>>>(Bh, Wc, Ah, n);
    k_gather_out<<<gatherBlocks, T>>>(Ah, out, bmu, bls, half, n);
}